// round 15
// baseline (speedup 1.0000x reference)
#include <cuda_runtime.h>

#define HH 512
#define WW 512
#define BC 6
#define NPIX (HH * WW)

// tile geometry: 32 wide x 16 tall outputs, 128 threads (32x4), 4 rows/thread,
// each thread handles 2 channels packed in f32x2.
#define TW 32
#define TH 16
#define HW 36    // TW + 4
#define HHALO 20 // TH + 4
#define NBLK 512 // (WW/TW)*(HH/TH) = 16*32 blocks per channel

typedef unsigned long long ull;

// ---- static device scratch (no runtime allocation allowed) ----
// State recycling: g_gmax starts zero (CUDA zero-init) and is re-zeroed by
// k_norm after its last reader, before the next replay's k_sobel atomics.
// g_pS/g_pS2 are plain overwritten stores each replay (no accumulation).
__device__ float g_gmag[BC * NPIX];
__device__ float g_xnA[BC * NPIX];
__device__ float g_ynA[BC * NPIX];
__device__ float g_xnB[BC * NPIX];
__device__ float g_ynB[BC * NPIX];
__device__ int   g_gmax[BC];
__device__ float g_pS[BC][NBLK];    // per-block partial sum of angles
__device__ float g_pS2[BC][NBLK];   // per-block partial sum of angle^2

__device__ __forceinline__ int refl(int i, int n) {
    if (i < 0) i = -i;
    if (i >= n) i = 2 * (n - 1) - i;
    return i;
}

__device__ __forceinline__ float tanh_fast(float x) {
    float y;
    asm("tanh.approx.f32 %0, %1;" : "=f"(y) : "f"(x));
    return y;
}

// ---- packed f32x2 helpers (Blackwell) ----
__device__ __forceinline__ ull pk(float a, float b) {
    ull r; asm("mov.b64 %0, {%1, %2};" : "=l"(r) : "f"(a), "f"(b)); return r;
}
__device__ __forceinline__ void upk(ull v, float& a, float& b) {
    asm("mov.b64 {%0, %1}, %2;" : "=f"(a), "=f"(b) : "l"(v));
}
__device__ __forceinline__ ull mul2(ull a, ull b) {
    ull r; asm("mul.rn.f32x2 %0, %1, %2;" : "=l"(r) : "l"(a), "l"(b)); return r;
}
__device__ __forceinline__ ull fma2(ull a, ull b, ull c) {
    ull r; asm("fma.rn.f32x2 %0, %1, %2, %3;" : "=l"(r) : "l"(a), "l"(b), "l"(c)); return r;
}

// Branchless Cephes-style atan, max err ~2e-7 rad.
__device__ __forceinline__ float atan_fast(float x) {
    float ax = fabsf(x);
    bool big = ax > 2.414213562f;     // tan(3pi/8)
    bool mid = ax > 0.4142135624f;    // tan(pi/8)
    float num = big ? -1.0f : ax - 1.0f;
    float den = big ? ax : ax + 1.0f;
    float r = mid ? __fdividef(num, den) : ax;
    float base = big ? 1.57079632679f : (mid ? 0.78539816340f : 0.0f);
    float z = r * r;
    float p = fmaf(fmaf(fmaf(8.05374449538e-2f, z, -1.38776856032e-1f), z,
                        1.99777106478e-1f), z, -3.33329491539e-1f);
    float res = base + fmaf(p * z, r, r);
    return copysignf(res, x);
}

// -------------------- Sobel + rotate + gmag max --------------------
// 4 vertical px per thread: 6x3 input window (18 LDG) for 4 outputs.
__global__ void __launch_bounds__(256) k_sobel(const float* __restrict__ img) {
    int c = blockIdx.z;
    const float* p = img + c * NPIX;
    int x  = blockIdx.x * 32 + threadIdx.x;
    int y0 = blockIdx.y * 32 + threadIdx.y * 4;
    int tid = threadIdx.y * 32 + threadIdx.x;

    float a[6][3];
#pragma unroll
    for (int r = 0; r < 6; r++) {
#pragma unroll
        for (int i = 0; i < 3; i++) {
            int yy = y0 + r - 1, xx = x + i - 1;
            a[r][i] = ((unsigned)yy < HH && (unsigned)xx < WW) ? p[yy * WW + xx] : 0.f;
        }
    }

    float mloc = 0.f;
#pragma unroll
    for (int k = 0; k < 4; k++) {
        float gx = (a[k][2] - a[k][0]) + 2.f * (a[k + 1][2] - a[k + 1][0]) + (a[k + 2][2] - a[k + 2][0]);
        float gy = (a[k + 2][0] - a[k][0]) + 2.f * (a[k + 2][1] - a[k][1]) + (a[k + 2][2] - a[k][2]);
        // uniform input scale (imgmax) dropped: results are scale-invariant
        gx = fmaxf(gx, 1e-12f);
        gy = fmaxf(gy, 1e-12f);

        float gm = sqrtf(fmaf(gx, gx, gy * gy));
        float invg = 1.0f / gm;
        float x0 = gx * invg, y0v = gy * invg;
        const float ct = -4.3711388e-08f, st = 1.0f;  // fp32 cos/sin(pi/2)
        float xn = x0 * ct - y0v * st;
        float yn = y0v * ct + x0 * st;

        int o = c * NPIX + (y0 + k) * WW + x;
        g_gmag[o] = gm;
        g_xnA[o]  = xn;
        g_ynA[o]  = yn;
        mloc = fmaxf(mloc, gm);
    }

    __shared__ float sm[8];
    int lane = tid & 31, warp = tid >> 5;
    float m = mloc;
#pragma unroll
    for (int off = 16; off; off >>= 1) m = fmaxf(m, __shfl_xor_sync(0xffffffffu, m, off));
    if (lane == 0) sm[warp] = m;
    __syncthreads();
    if (tid == 0) {
#pragma unroll
        for (int i = 1; i < 8; i++) m = fmaxf(m, sm[i]);
        atomicMax(&g_gmax[c], __float_as_int(m));
    }
}

// -------------------- channel-paired shared tile loader (3 arrays) ----------
__device__ __forceinline__ void load_tile2(
    ull (*sXN)[HW], ull (*sYN)[HW], ull (*sGN)[HW],
    const float* __restrict__ gm0, const float* __restrict__ gm1,
    const float* __restrict__ xi0, const float* __restrict__ xi1,
    const float* __restrict__ yi0, const float* __restrict__ yi1,
    float ginv0, float ginv1, int bx0, int by0, int tid) {
    bool interior = (bx0 >= 0) && (by0 >= 0) && (bx0 + HW <= WW) && (by0 + HHALO <= HH);
    for (int i = tid; i < HHALO * HW; i += 128) {
        int ly = i / HW, lx = i - ly * HW;
        int o;
        if (interior) {
            o = (by0 + ly) * WW + bx0 + lx;
        } else {
            o = refl(by0 + ly, HH) * WW + refl(bx0 + lx, WW);
        }
        sXN[ly][lx] = pk(xi0[o], xi1[o]);
        sYN[ly][lx] = pk(yi0[o], yi1[o]);
        sGN[ly][lx] = pk(gm0[o] * ginv0, gm1[o] * ginv1);
    }
}

// core 5x5 weighted accumulation: 4 consecutive rows x 2 channels per thread.
// R12 form (measured-fastest): hoisted upk of gn2 per position; scalar FADD
// differences feeding the scalar MUFU tanh; 6 f32x2 slots + 2 FADD + 2 MUFU
// per (position,center). 3 LDS.64 per neighbor position.
__device__ __forceinline__ void etf_core2(
    const ull (*sXN)[HW], const ull (*sYN)[HW], const ull (*sGN)[HW],
    int tx, int row0, ull* xr2, ull* yr2) {
    ull xc2[4], yc2[4];
    float gc0[4], gc1[4];
#pragma unroll
    for (int k = 0; k < 4; k++) {
        xc2[k] = sXN[row0 + 2 + k][tx + 2];
        yc2[k] = sYN[row0 + 2 + k][tx + 2];
        float g0, g1;
        upk(sGN[row0 + 2 + k][tx + 2], g0, g1);
        gc0[k] = g0; gc1[k] = g1;
        xr2[k] = 0ull; yr2[k] = 0ull;   // bits zero == (0.f, 0.f)
    }
#pragma unroll
    for (int r = 0; r < 8; r++) {
#pragma unroll
        for (int dx = 0; dx < 5; dx++) {
            ull xn2 = sXN[row0 + r][tx + dx];
            ull yn2 = sYN[row0 + r][tx + dx];
            ull gn2 = sGN[row0 + r][tx + dx];
            float g0, g1;
            upk(gn2, g0, g1);
#pragma unroll
            for (int k = 0; k < 4; k++) {
                if (r >= k && r <= k + 4) {   // static predicate, fully unrolled
                    float th0 = tanh_fast(g0 - gc0[k]);
                    float th1 = tanh_fast(g1 - gc1[k]);
                    ull th2 = pk(th0, th1);
                    ull dot2 = fma2(xc2[k], xn2, mul2(yc2[k], yn2));
                    ull u2 = fma2(th2, dot2, dot2);        // (1+tanh)*dot
                    ull t2 = mul2(gn2, u2);                // gn * (1+tanh) * dot
                    xr2[k] = fma2(xn2, t2, xr2[k]);
                    yr2[k] = fma2(yn2, t2, yr2[k]);
                }
            }
        }
    }
}

// -------------------- ETF iterations 1 & 2 (2 channels per block) ------------
__global__ void __launch_bounds__(128) k_iter(int sel) {
    __shared__ ull sXN[HHALO][HW];
    __shared__ ull sYN[HHALO][HW];
    __shared__ ull sGN[HHALO][HW];

    int c0 = blockIdx.z * 2, c1 = c0 + 1;
    const float* xiB = sel ? g_xnB : g_xnA;
    const float* yiB = sel ? g_ynB : g_ynA;
    float* xoB = sel ? g_xnA : g_xnB;
    float* yoB = sel ? g_ynA : g_ynB;

    float ginv0 = 1.0f / __int_as_float(g_gmax[c0]);
    float ginv1 = 1.0f / __int_as_float(g_gmax[c1]);
    int bx0 = blockIdx.x * TW - 2;
    int by0 = blockIdx.y * TH - 2;
    int tid = threadIdx.y * 32 + threadIdx.x;

    load_tile2(sXN, sYN, sGN,
               g_gmag + c0 * NPIX, g_gmag + c1 * NPIX,
               xiB + c0 * NPIX, xiB + c1 * NPIX,
               yiB + c0 * NPIX, yiB + c1 * NPIX,
               ginv0, ginv1, bx0, by0, tid);
    __syncthreads();

    int tx = threadIdx.x;
    int row0 = threadIdx.y * 4;
    int px = blockIdx.x * TW + tx;
    ull xr2[4], yr2[4];
    etf_core2(sXN, sYN, sGN, tx, row0, xr2, yr2);

#pragma unroll
    for (int k = 0; k < 4; k++) {
        float x0, x1, y0v, y1;
        upk(xr2[k], x0, x1);
        upk(yr2[k], y0v, y1);
        float i0 = rsqrtf(fmaf(x0, x0, y0v * y0v));
        float i1 = rsqrtf(fmaf(x1, x1, y1 * y1));
        int o = (blockIdx.y * TH + row0 + k) * WW + px;
        xoB[c0 * NPIX + o] = x0 * i0;
        yoB[c0 * NPIX + o] = y0v * i0;
        xoB[c1 * NPIX + o] = x1 * i1;
        yoB[c1 * NPIX + o] = y1 * i1;
    }
}

// -------------------- ETF iteration 3 fused with angle + partial stats -------
// Per-channel stats: fp32 warp shuffles -> smem block stage -> plain STG of
// one fp32 partial pair per channel per block (NO global atomics).
__global__ void __launch_bounds__(128) k_iter3(float* __restrict__ out) {
    __shared__ ull   sXN[HHALO][HW];
    __shared__ ull   sYN[HHALO][HW];
    __shared__ ull   sGN[HHALO][HW];
    __shared__ float sS[4][4];   // [warp][s0,s20,s1,s21]

    int c0 = blockIdx.z * 2, c1 = c0 + 1;
    float ginv0 = 1.0f / __int_as_float(g_gmax[c0]);
    float ginv1 = 1.0f / __int_as_float(g_gmax[c1]);
    int bx0 = blockIdx.x * TW - 2;
    int by0 = blockIdx.y * TH - 2;
    int tid = threadIdx.y * 32 + threadIdx.x;

    load_tile2(sXN, sYN, sGN,
               g_gmag + c0 * NPIX, g_gmag + c1 * NPIX,
               g_xnA + c0 * NPIX, g_xnA + c1 * NPIX,   // iter3 reads A
               g_ynA + c0 * NPIX, g_ynA + c1 * NPIX,
               ginv0, ginv1, bx0, by0, tid);
    __syncthreads();

    int tx = threadIdx.x;
    int row0 = threadIdx.y * 4;
    int px = blockIdx.x * TW + tx;
    ull xr2[4], yr2[4];
    etf_core2(sXN, sYN, sGN, tx, row0, xr2, yr2);

    float s0 = 0.f, s20 = 0.f, s1 = 0.f, s21 = 0.f;
#pragma unroll
    for (int k = 0; k < 4; k++) {
        float x0, x1, y0v, y1;
        upk(xr2[k], x0, x1);
        upk(yr2[k], y0v, y1);
        int o = (blockIdx.y * TH + row0 + k) * WW + px;
        // normalization cancels inside atan(-y/x); divide directly
        float a0 = atan_fast(__fdividef(-y0v, x0)) * 57.2957795131f;
        float a1 = atan_fast(__fdividef(-y1, x1)) * 57.2957795131f;
        out[c0 * NPIX + o] = a0;
        out[c1 * NPIX + o] = a1;
        s0 += a0; s20 = fmaf(a0, a0, s20);
        s1 += a1; s21 = fmaf(a1, a1, s21);
    }

#pragma unroll
    for (int off = 16; off; off >>= 1) {
        s0  += __shfl_xor_sync(0xffffffffu, s0, off);
        s20 += __shfl_xor_sync(0xffffffffu, s20, off);
        s1  += __shfl_xor_sync(0xffffffffu, s1, off);
        s21 += __shfl_xor_sync(0xffffffffu, s21, off);
    }
    int lane = tid & 31, warp = tid >> 5;
    if (lane == 0) {
        sS[warp][0] = s0; sS[warp][1] = s20;
        sS[warp][2] = s1; sS[warp][3] = s21;
    }
    __syncthreads();
    if (tid == 0) {
        int bid = blockIdx.y * (WW / TW) + blockIdx.x;   // [0, NBLK)
        g_pS[c0][bid]  = sS[0][0] + sS[1][0] + sS[2][0] + sS[3][0];
        g_pS2[c0][bid] = sS[0][1] + sS[1][1] + sS[2][1] + sS[3][1];
        g_pS[c1][bid]  = sS[0][2] + sS[1][2] + sS[2][2] + sS[3][2];
        g_pS2[c1][bid] = sS[0][3] + sS[1][3] + sS[2][3] + sS[3][3];
    }
}

// -------------------- normalize (float4) + reduce partials + recycle --------
// Every block independently reduces its channel's NBLK=512 partials (each of
// the 256 threads folds two; L2-hit loads) — cheaper than a separate stats
// kernel or global atomics.
__global__ void __launch_bounds__(256) k_norm(float* __restrict__ out) {
    __shared__ float red[16];
    __shared__ float smu, sinv;
    int c = blockIdx.y;
    int t = threadIdx.x;

    float s  = g_pS[c][t]  + g_pS[c][t + 256];
    float s2 = g_pS2[c][t] + g_pS2[c][t + 256];
#pragma unroll
    for (int off = 16; off; off >>= 1) {
        s  += __shfl_xor_sync(0xffffffffu, s, off);
        s2 += __shfl_xor_sync(0xffffffffu, s2, off);
    }
    int lane = t & 31, warp = t >> 5;
    if (lane == 0) { red[warp] = s; red[8 + warp] = s2; }
    __syncthreads();
    if (t == 0) {
        double S = 0.0, S2 = 0.0;
#pragma unroll
        for (int w = 0; w < 8; w++) { S += (double)red[w]; S2 += (double)red[8 + w]; }
        double mean = S / (double)NPIX;
        double var  = S2 / (double)NPIX - mean * mean;
        smu  = (float)mean;
        sinv = (float)(1.0 / sqrt(var + 1e-5));
        if (blockIdx.x == 0) g_gmax[c] = 0;   // recycle for next replay
    }
    __syncthreads();

    float4* o4 = (float4*)(out + c * NPIX);
    int i = blockIdx.x * blockDim.x + t;
    float4 v = o4[i];
    float mu = smu, is = sinv;
    v.x = (v.x - mu) * is;
    v.y = (v.y - mu) * is;
    v.z = (v.z - mu) * is;
    v.w = (v.w - mu) * is;
    o4[i] = v;
}

extern "C" void kernel_launch(void* const* d_in, const int* in_sizes, int n_in,
                              void* d_out, int out_size) {
    const float* img = (const float*)d_in[0];
    float* out = (float*)d_out;

    k_sobel<<<dim3(WW / 32, HH / 32, BC), dim3(32, 8)>>>(img);
    k_iter<<<dim3(WW / TW, HH / TH, BC / 2), dim3(32, 4)>>>(0);   // A -> B
    k_iter<<<dim3(WW / TW, HH / TH, BC / 2), dim3(32, 4)>>>(1);   // B -> A
    k_iter3<<<dim3(WW / TW, HH / TH, BC / 2), dim3(32, 4)>>>(out);// A -> out (+partials)
    k_norm<<<dim3(NPIX / 4 / 256, BC), 256>>>(out);
}

// round 16
// speedup vs baseline: 1.1050x; 1.1050x over previous
#include <cuda_runtime.h>

#define HH 512
#define WW 512
#define BC 6
#define NPIX (HH * WW)

// tile geometry: 32 wide x 16 tall outputs, 128 threads (32x4), 4 rows/thread,
// each thread handles 2 channels packed in f32x2.
#define TW 32
#define TH 16
#define HW 36    // TW + 4
#define HHALO 20 // TH + 4

typedef unsigned long long ull;

// ---- static device scratch (no runtime allocation allowed) ----
// State recycling: counters start zero (CUDA zero-init) and every replay
// re-zeros them at a point ordered before their next use:
//   g_sum/g_sumsq : zeroed in k_sobel (before k_iter3's atomics)
//   g_gmax        : zeroed in k_norm  (after its last reader)
__device__ float g_gmag[BC * NPIX];
__device__ float g_xnA[BC * NPIX];
__device__ float g_ynA[BC * NPIX];
__device__ float g_xnB[BC * NPIX];
__device__ float g_ynB[BC * NPIX];
__device__ int    g_gmax[BC];
__device__ double g_sum[BC];
__device__ double g_sumsq[BC];

__device__ __forceinline__ int refl(int i, int n) {
    if (i < 0) i = -i;
    if (i >= n) i = 2 * (n - 1) - i;
    return i;
}

__device__ __forceinline__ float tanh_fast(float x) {
    float y;
    asm("tanh.approx.f32 %0, %1;" : "=f"(y) : "f"(x));
    return y;
}

// ---- packed f32x2 helpers (Blackwell) ----
__device__ __forceinline__ ull pk(float a, float b) {
    ull r; asm("mov.b64 %0, {%1, %2};" : "=l"(r) : "f"(a), "f"(b)); return r;
}
__device__ __forceinline__ void upk(ull v, float& a, float& b) {
    asm("mov.b64 {%0, %1}, %2;" : "=f"(a), "=f"(b) : "l"(v));
}
__device__ __forceinline__ ull mul2(ull a, ull b) {
    ull r; asm("mul.rn.f32x2 %0, %1, %2;" : "=l"(r) : "l"(a), "l"(b)); return r;
}
__device__ __forceinline__ ull fma2(ull a, ull b, ull c) {
    ull r; asm("fma.rn.f32x2 %0, %1, %2, %3;" : "=l"(r) : "l"(a), "l"(b), "l"(c)); return r;
}

// Branchless Cephes-style atan, max err ~2e-7 rad.
__device__ __forceinline__ float atan_fast(float x) {
    float ax = fabsf(x);
    bool big = ax > 2.414213562f;     // tan(3pi/8)
    bool mid = ax > 0.4142135624f;    // tan(pi/8)
    float num = big ? -1.0f : ax - 1.0f;
    float den = big ? ax : ax + 1.0f;
    float r = mid ? __fdividef(num, den) : ax;
    float base = big ? 1.57079632679f : (mid ? 0.78539816340f : 0.0f);
    float z = r * r;
    float p = fmaf(fmaf(fmaf(8.05374449538e-2f, z, -1.38776856032e-1f), z,
                        1.99777106478e-1f), z, -3.33329491539e-1f);
    float res = base + fmaf(p * z, r, r);
    return copysignf(res, x);
}

// -------------------- Sobel + rotate + gmag max --------------------
// 4 vertical px per thread: 6x3 input window (18 LDG) for 4 outputs.
// Interior blocks (77%) skip the per-load bounds predicates.
__global__ void __launch_bounds__(256) k_sobel(const float* __restrict__ img) {
    int c = blockIdx.z;
    const float* p = img + c * NPIX;
    int x  = blockIdx.x * 32 + threadIdx.x;
    int y0 = blockIdx.y * 32 + threadIdx.y * 4;
    int tid = threadIdx.y * 32 + threadIdx.x;

    if (blockIdx.x == 0 && blockIdx.y == 0 && tid == 0) {
        g_sum[c] = 0.0;
        g_sumsq[c] = 0.0;
    }

    float a[6][3];
    bool interior = (blockIdx.x > 0) && (blockIdx.x < (WW / 32) - 1) &&
                    (blockIdx.y > 0) && (blockIdx.y < (HH / 32) - 1);
    if (interior) {
#pragma unroll
        for (int r = 0; r < 6; r++)
#pragma unroll
            for (int i = 0; i < 3; i++)
                a[r][i] = p[(y0 + r - 1) * WW + x + i - 1];
    } else {
#pragma unroll
        for (int r = 0; r < 6; r++)
#pragma unroll
            for (int i = 0; i < 3; i++) {
                int yy = y0 + r - 1, xx = x + i - 1;
                a[r][i] = ((unsigned)yy < HH && (unsigned)xx < WW) ? p[yy * WW + xx] : 0.f;
            }
    }

    float mloc = 0.f;
#pragma unroll
    for (int k = 0; k < 4; k++) {
        float gx = (a[k][2] - a[k][0]) + 2.f * (a[k + 1][2] - a[k + 1][0]) + (a[k + 2][2] - a[k + 2][0]);
        float gy = (a[k + 2][0] - a[k][0]) + 2.f * (a[k + 2][1] - a[k][1]) + (a[k + 2][2] - a[k][2]);
        // uniform input scale (imgmax) dropped: results are scale-invariant
        gx = fmaxf(gx, 1e-12f);
        gy = fmaxf(gy, 1e-12f);

        float gm = sqrtf(fmaf(gx, gx, gy * gy));
        float invg = 1.0f / gm;
        float x0 = gx * invg, y0v = gy * invg;
        const float ct = -4.3711388e-08f, st = 1.0f;  // fp32 cos/sin(pi/2)
        float xn = x0 * ct - y0v * st;
        float yn = y0v * ct + x0 * st;

        int o = c * NPIX + (y0 + k) * WW + x;
        g_gmag[o] = gm;
        g_xnA[o]  = xn;
        g_ynA[o]  = yn;
        mloc = fmaxf(mloc, gm);
    }

    __shared__ float sm[8];
    int lane = tid & 31, warp = tid >> 5;
    float m = mloc;
#pragma unroll
    for (int off = 16; off; off >>= 1) m = fmaxf(m, __shfl_xor_sync(0xffffffffu, m, off));
    if (lane == 0) sm[warp] = m;
    __syncthreads();
    if (tid == 0) {
#pragma unroll
        for (int i = 1; i < 8; i++) m = fmaxf(m, sm[i]);
        atomicMax(&g_gmax[c], __float_as_int(m));
    }
}

// -------------------- channel-paired shared tile loader (3 arrays) ----------
__device__ __forceinline__ void load_tile2(
    ull (*sXN)[HW], ull (*sYN)[HW], ull (*sGN)[HW],
    const float* __restrict__ gm0, const float* __restrict__ gm1,
    const float* __restrict__ xi0, const float* __restrict__ xi1,
    const float* __restrict__ yi0, const float* __restrict__ yi1,
    float ginv0, float ginv1, int bx0, int by0, int tid) {
    bool interior = (bx0 >= 0) && (by0 >= 0) && (bx0 + HW <= WW) && (by0 + HHALO <= HH);
    for (int i = tid; i < HHALO * HW; i += 128) {
        int ly = i / HW, lx = i - ly * HW;
        int o;
        if (interior) {
            o = (by0 + ly) * WW + bx0 + lx;
        } else {
            o = refl(by0 + ly, HH) * WW + refl(bx0 + lx, WW);
        }
        sXN[ly][lx] = pk(xi0[o], xi1[o]);
        sYN[ly][lx] = pk(yi0[o], yi1[o]);
        sGN[ly][lx] = pk(gm0[o] * ginv0, gm1[o] * ginv1);
    }
}

// core 5x5 weighted accumulation: 4 consecutive rows x 2 channels per thread.
// Measured-fastest (R12) form: hoisted upk of gn2 per position; scalar FADD
// differences feeding the scalar MUFU tanh; 6 f32x2 + 2 FADD + 2 MUFU per
// (position,center). 3 LDS.64 per neighbor position.
__device__ __forceinline__ void etf_core2(
    const ull (*sXN)[HW], const ull (*sYN)[HW], const ull (*sGN)[HW],
    int tx, int row0, ull* xr2, ull* yr2) {
    ull xc2[4], yc2[4];
    float gc0[4], gc1[4];
#pragma unroll
    for (int k = 0; k < 4; k++) {
        xc2[k] = sXN[row0 + 2 + k][tx + 2];
        yc2[k] = sYN[row0 + 2 + k][tx + 2];
        float g0, g1;
        upk(sGN[row0 + 2 + k][tx + 2], g0, g1);
        gc0[k] = g0; gc1[k] = g1;
        xr2[k] = 0ull; yr2[k] = 0ull;   // bits zero == (0.f, 0.f)
    }
#pragma unroll
    for (int r = 0; r < 8; r++) {
#pragma unroll
        for (int dx = 0; dx < 5; dx++) {
            ull xn2 = sXN[row0 + r][tx + dx];
            ull yn2 = sYN[row0 + r][tx + dx];
            ull gn2 = sGN[row0 + r][tx + dx];
            float g0, g1;
            upk(gn2, g0, g1);
#pragma unroll
            for (int k = 0; k < 4; k++) {
                if (r >= k && r <= k + 4) {   // static predicate, fully unrolled
                    float th0 = tanh_fast(g0 - gc0[k]);
                    float th1 = tanh_fast(g1 - gc1[k]);
                    ull th2 = pk(th0, th1);
                    ull dot2 = fma2(xc2[k], xn2, mul2(yc2[k], yn2));
                    ull u2 = fma2(th2, dot2, dot2);        // (1+tanh)*dot
                    ull t2 = mul2(gn2, u2);                // gn * (1+tanh) * dot
                    xr2[k] = fma2(xn2, t2, xr2[k]);
                    yr2[k] = fma2(yn2, t2, yr2[k]);
                }
            }
        }
    }
}

// -------------------- ETF iterations 1 & 2 (2 channels per block) ------------
__global__ void __launch_bounds__(128) k_iter(int sel) {
    __shared__ ull sXN[HHALO][HW];
    __shared__ ull sYN[HHALO][HW];
    __shared__ ull sGN[HHALO][HW];

    int c0 = blockIdx.z * 2, c1 = c0 + 1;
    const float* xiB = sel ? g_xnB : g_xnA;
    const float* yiB = sel ? g_ynB : g_ynA;
    float* xoB = sel ? g_xnA : g_xnB;
    float* yoB = sel ? g_ynA : g_ynB;

    float ginv0 = 1.0f / __int_as_float(g_gmax[c0]);
    float ginv1 = 1.0f / __int_as_float(g_gmax[c1]);
    int bx0 = blockIdx.x * TW - 2;
    int by0 = blockIdx.y * TH - 2;
    int tid = threadIdx.y * 32 + threadIdx.x;

    load_tile2(sXN, sYN, sGN,
               g_gmag + c0 * NPIX, g_gmag + c1 * NPIX,
               xiB + c0 * NPIX, xiB + c1 * NPIX,
               yiB + c0 * NPIX, yiB + c1 * NPIX,
               ginv0, ginv1, bx0, by0, tid);
    __syncthreads();

    int tx = threadIdx.x;
    int row0 = threadIdx.y * 4;
    int px = blockIdx.x * TW + tx;
    ull xr2[4], yr2[4];
    etf_core2(sXN, sYN, sGN, tx, row0, xr2, yr2);

#pragma unroll
    for (int k = 0; k < 4; k++) {
        float x0, x1, y0v, y1;
        upk(xr2[k], x0, x1);
        upk(yr2[k], y0v, y1);
        float i0 = rsqrtf(fmaf(x0, x0, y0v * y0v));
        float i1 = rsqrtf(fmaf(x1, x1, y1 * y1));
        int o = (blockIdx.y * TH + row0 + k) * WW + px;
        xoB[c0 * NPIX + o] = x0 * i0;
        yoB[c0 * NPIX + o] = y0v * i0;
        xoB[c1 * NPIX + o] = x1 * i1;
        yoB[c1 * NPIX + o] = y1 * i1;
    }
}

// -------------------- ETF iteration 3 fused with angle + stats ---------------
// Per-channel stats: fp32 warp shuffles -> smem block stage -> ONE fp64 atomic
// pair per channel per block (measured-best epilogue; the STG-partials +
// k_norm-re-reduce variant was slower overall in R14/R15).
__global__ void __launch_bounds__(128) k_iter3(float* __restrict__ out) {
    __shared__ ull   sXN[HHALO][HW];
    __shared__ ull   sYN[HHALO][HW];
    __shared__ ull   sGN[HHALO][HW];
    __shared__ float sS[4][4];   // [warp][s0,s20,s1,s21]

    int c0 = blockIdx.z * 2, c1 = c0 + 1;
    float ginv0 = 1.0f / __int_as_float(g_gmax[c0]);
    float ginv1 = 1.0f / __int_as_float(g_gmax[c1]);
    int bx0 = blockIdx.x * TW - 2;
    int by0 = blockIdx.y * TH - 2;
    int tid = threadIdx.y * 32 + threadIdx.x;

    load_tile2(sXN, sYN, sGN,
               g_gmag + c0 * NPIX, g_gmag + c1 * NPIX,
               g_xnA + c0 * NPIX, g_xnA + c1 * NPIX,   // iter3 reads A
               g_ynA + c0 * NPIX, g_ynA + c1 * NPIX,
               ginv0, ginv1, bx0, by0, tid);
    __syncthreads();

    int tx = threadIdx.x;
    int row0 = threadIdx.y * 4;
    int px = blockIdx.x * TW + tx;
    ull xr2[4], yr2[4];
    etf_core2(sXN, sYN, sGN, tx, row0, xr2, yr2);

    float s0 = 0.f, s20 = 0.f, s1 = 0.f, s21 = 0.f;
#pragma unroll
    for (int k = 0; k < 4; k++) {
        float x0, x1, y0v, y1;
        upk(xr2[k], x0, x1);
        upk(yr2[k], y0v, y1);
        int o = (blockIdx.y * TH + row0 + k) * WW + px;
        // normalization cancels inside atan(-y/x); divide directly
        float a0 = atan_fast(__fdividef(-y0v, x0)) * 57.2957795131f;
        float a1 = atan_fast(__fdividef(-y1, x1)) * 57.2957795131f;
        out[c0 * NPIX + o] = a0;
        out[c1 * NPIX + o] = a1;
        s0 += a0; s20 = fmaf(a0, a0, s20);
        s1 += a1; s21 = fmaf(a1, a1, s21);
    }

#pragma unroll
    for (int off = 16; off; off >>= 1) {
        s0  += __shfl_xor_sync(0xffffffffu, s0, off);
        s20 += __shfl_xor_sync(0xffffffffu, s20, off);
        s1  += __shfl_xor_sync(0xffffffffu, s1, off);
        s21 += __shfl_xor_sync(0xffffffffu, s21, off);
    }
    int lane = tid & 31, warp = tid >> 5;
    if (lane == 0) {
        sS[warp][0] = s0; sS[warp][1] = s20;
        sS[warp][2] = s1; sS[warp][3] = s21;
    }
    __syncthreads();
    if (tid == 0) {
        float t0 = sS[0][0] + sS[1][0] + sS[2][0] + sS[3][0];
        float t1 = sS[0][1] + sS[1][1] + sS[2][1] + sS[3][1];
        float t2 = sS[0][2] + sS[1][2] + sS[2][2] + sS[3][2];
        float t3 = sS[0][3] + sS[1][3] + sS[2][3] + sS[3][3];
        atomicAdd(&g_sum[c0], (double)t0);     // return unused -> REDG
        atomicAdd(&g_sumsq[c0], (double)t1);
        atomicAdd(&g_sum[c1], (double)t2);
        atomicAdd(&g_sumsq[c1], (double)t3);
    }
}

// -------------------- normalize (float4) + recycle state --------------------
__global__ void __launch_bounds__(256) k_norm(float* __restrict__ out) {
    __shared__ float smu, sinv;
    int c = blockIdx.y;
    if (threadIdx.x == 0) {
        double mean = g_sum[c] / (double)NPIX;
        double var  = g_sumsq[c] / (double)NPIX - mean * mean;
        smu  = (float)mean;
        sinv = (float)(1.0 / sqrt(var + 1e-5));
        if (blockIdx.x == 0) g_gmax[c] = 0;   // recycle for next replay
    }
    __syncthreads();
    float4* o4 = (float4*)(out + c * NPIX);
    int i = blockIdx.x * blockDim.x + threadIdx.x;
    float4 v = o4[i];
    float mu = smu, is = sinv;
    v.x = (v.x - mu) * is;
    v.y = (v.y - mu) * is;
    v.z = (v.z - mu) * is;
    v.w = (v.w - mu) * is;
    o4[i] = v;
}

extern "C" void kernel_launch(void* const* d_in, const int* in_sizes, int n_in,
                              void* d_out, int out_size) {
    const float* img = (const float*)d_in[0];
    float* out = (float*)d_out;

    k_sobel<<<dim3(WW / 32, HH / 32, BC), dim3(32, 8)>>>(img);
    k_iter<<<dim3(WW / TW, HH / TH, BC / 2), dim3(32, 4)>>>(0);   // A -> B
    k_iter<<<dim3(WW / TW, HH / TH, BC / 2), dim3(32, 4)>>>(1);   // B -> A
    k_iter3<<<dim3(WW / TW, HH / TH, BC / 2), dim3(32, 4)>>>(out);// A -> out (+stats)
    k_norm<<<dim3(NPIX / 4 / 256, BC), 256>>>(out);
}

// round 17
// speedup vs baseline: 1.1358x; 1.0279x over previous
#include <cuda_runtime.h>

#define HH 512
#define WW 512
#define BC 6
#define NPIX (HH * WW)

// tile geometry: 32 wide x 16 tall outputs, 128 threads (32x4), 4 rows/thread,
// each thread handles 2 channels packed in f32x2.
#define TW 32
#define TH 16
#define HW 36    // TW + 4
#define HHALO 20 // TH + 4

typedef unsigned long long ull;

// ---- static device scratch (no runtime allocation allowed) ----
// State recycling: counters start zero (CUDA zero-init) and every replay
// re-zeros them at a point ordered before their next use:
//   g_sum/g_sumsq : zeroed in k_sobel (before k_iter3's atomics)
//   g_gmax        : zeroed in k_norm  (after its last reader)
__device__ float  g_gmag[BC * NPIX];
__device__ float2 g_xyA[BC * NPIX];   // (xn, yn) interleaved per channel
__device__ float2 g_xyB[BC * NPIX];
__device__ int    g_gmax[BC];
__device__ double g_sum[BC];
__device__ double g_sumsq[BC];

__device__ __forceinline__ int refl(int i, int n) {
    if (i < 0) i = -i;
    if (i >= n) i = 2 * (n - 1) - i;
    return i;
}

__device__ __forceinline__ float tanh_fast(float x) {
    float y;
    asm("tanh.approx.f32 %0, %1;" : "=f"(y) : "f"(x));
    return y;
}

// ---- packed f32x2 helpers (Blackwell) ----
__device__ __forceinline__ ull pk(float a, float b) {
    ull r; asm("mov.b64 %0, {%1, %2};" : "=l"(r) : "f"(a), "f"(b)); return r;
}
__device__ __forceinline__ void upk(ull v, float& a, float& b) {
    asm("mov.b64 {%0, %1}, %2;" : "=f"(a), "=f"(b) : "l"(v));
}
__device__ __forceinline__ ull mul2(ull a, ull b) {
    ull r; asm("mul.rn.f32x2 %0, %1, %2;" : "=l"(r) : "l"(a), "l"(b)); return r;
}
__device__ __forceinline__ ull fma2(ull a, ull b, ull c) {
    ull r; asm("fma.rn.f32x2 %0, %1, %2, %3;" : "=l"(r) : "l"(a), "l"(b), "l"(c)); return r;
}

// Branchless Cephes-style atan, max err ~2e-7 rad.
__device__ __forceinline__ float atan_fast(float x) {
    float ax = fabsf(x);
    bool big = ax > 2.414213562f;     // tan(3pi/8)
    bool mid = ax > 0.4142135624f;    // tan(pi/8)
    float num = big ? -1.0f : ax - 1.0f;
    float den = big ? ax : ax + 1.0f;
    float r = mid ? __fdividef(num, den) : ax;
    float base = big ? 1.57079632679f : (mid ? 0.78539816340f : 0.0f);
    float z = r * r;
    float p = fmaf(fmaf(fmaf(8.05374449538e-2f, z, -1.38776856032e-1f), z,
                        1.99777106478e-1f), z, -3.33329491539e-1f);
    float res = base + fmaf(p * z, r, r);
    return copysignf(res, x);
}

// -------------------- Sobel + rotate + gmag max --------------------
// 4 vertical px per thread: 6x3 input window (18 LDG) for 4 outputs.
// Interior blocks (77%) skip the per-load bounds predicates.
__global__ void __launch_bounds__(256) k_sobel(const float* __restrict__ img) {
    int c = blockIdx.z;
    const float* p = img + c * NPIX;
    int x  = blockIdx.x * 32 + threadIdx.x;
    int y0 = blockIdx.y * 32 + threadIdx.y * 4;
    int tid = threadIdx.y * 32 + threadIdx.x;

    if (blockIdx.x == 0 && blockIdx.y == 0 && tid == 0) {
        g_sum[c] = 0.0;
        g_sumsq[c] = 0.0;
    }

    float a[6][3];
    bool interior = (blockIdx.x > 0) && (blockIdx.x < (WW / 32) - 1) &&
                    (blockIdx.y > 0) && (blockIdx.y < (HH / 32) - 1);
    if (interior) {
#pragma unroll
        for (int r = 0; r < 6; r++)
#pragma unroll
            for (int i = 0; i < 3; i++)
                a[r][i] = p[(y0 + r - 1) * WW + x + i - 1];
    } else {
#pragma unroll
        for (int r = 0; r < 6; r++)
#pragma unroll
            for (int i = 0; i < 3; i++) {
                int yy = y0 + r - 1, xx = x + i - 1;
                a[r][i] = ((unsigned)yy < HH && (unsigned)xx < WW) ? p[yy * WW + xx] : 0.f;
            }
    }

    float mloc = 0.f;
#pragma unroll
    for (int k = 0; k < 4; k++) {
        float gx = (a[k][2] - a[k][0]) + 2.f * (a[k + 1][2] - a[k + 1][0]) + (a[k + 2][2] - a[k + 2][0]);
        float gy = (a[k + 2][0] - a[k][0]) + 2.f * (a[k + 2][1] - a[k][1]) + (a[k + 2][2] - a[k][2]);
        // uniform input scale (imgmax) dropped: results are scale-invariant
        gx = fmaxf(gx, 1e-12f);
        gy = fmaxf(gy, 1e-12f);

        float gm = sqrtf(fmaf(gx, gx, gy * gy));
        float invg = 1.0f / gm;
        float x0 = gx * invg, y0v = gy * invg;
        const float ct = -4.3711388e-08f, st = 1.0f;  // fp32 cos/sin(pi/2)
        float xn = x0 * ct - y0v * st;
        float yn = y0v * ct + x0 * st;

        int o = c * NPIX + (y0 + k) * WW + x;
        g_gmag[o] = gm;
        g_xyA[o]  = make_float2(xn, yn);
        mloc = fmaxf(mloc, gm);
    }

    __shared__ float sm[8];
    int lane = tid & 31, warp = tid >> 5;
    float m = mloc;
#pragma unroll
    for (int off = 16; off; off >>= 1) m = fmaxf(m, __shfl_xor_sync(0xffffffffu, m, off));
    if (lane == 0) sm[warp] = m;
    __syncthreads();
    if (tid == 0) {
#pragma unroll
        for (int i = 1; i < 8; i++) m = fmaxf(m, sm[i]);
        atomicMax(&g_gmax[c], __float_as_int(m));
    }
}

// -------------------- channel-paired shared tile loader ----------------------
// sXY[.] = (xn2, yn2) as one 16B element -> single LDS.128 in the core.
__device__ __forceinline__ void load_tile2(
    ulonglong2 (*sXY)[HW], ull (*sGN)[HW],
    const float* __restrict__ gm0, const float* __restrict__ gm1,
    const float2* __restrict__ xy0, const float2* __restrict__ xy1,
    float ginv0, float ginv1, int bx0, int by0, int tid) {
    bool interior = (bx0 >= 0) && (by0 >= 0) && (bx0 + HW <= WW) && (by0 + HHALO <= HH);
    for (int i = tid; i < HHALO * HW; i += 128) {
        int ly = i / HW, lx = i - ly * HW;
        int o;
        if (interior) {
            o = (by0 + ly) * WW + bx0 + lx;
        } else {
            o = refl(by0 + ly, HH) * WW + refl(bx0 + lx, WW);
        }
        float2 a = xy0[o];
        float2 b = xy1[o];
        ulonglong2 v;
        v.x = pk(a.x, b.x);   // xn2
        v.y = pk(a.y, b.y);   // yn2
        sXY[ly][lx] = v;      // STS.128
        sGN[ly][lx] = pk(gm0[o] * ginv0, gm1[o] * ginv1);
    }
}

// core 5x5 weighted accumulation: 4 consecutive rows x 2 channels per thread.
// Measured-fastest (R12) math; 2 LDS (one .128 + one .64) per neighbor
// position; 6 f32x2 + 2 FADD + 2 MUFU per (position,center).
__device__ __forceinline__ void etf_core2(
    const ulonglong2 (*sXY)[HW], const ull (*sGN)[HW],
    int tx, int row0, ull* xr2, ull* yr2) {
    ull xc2[4], yc2[4];
    float gc0[4], gc1[4];
#pragma unroll
    for (int k = 0; k < 4; k++) {
        ulonglong2 cv = sXY[row0 + 2 + k][tx + 2];
        xc2[k] = cv.x;
        yc2[k] = cv.y;
        float g0, g1;
        upk(sGN[row0 + 2 + k][tx + 2], g0, g1);
        gc0[k] = g0; gc1[k] = g1;
        xr2[k] = 0ull; yr2[k] = 0ull;   // bits zero == (0.f, 0.f)
    }
#pragma unroll
    for (int r = 0; r < 8; r++) {
#pragma unroll
        for (int dx = 0; dx < 5; dx++) {
            ulonglong2 v = sXY[row0 + r][tx + dx];   // LDS.128: xn2 + yn2
            ull xn2 = v.x, yn2 = v.y;
            ull gn2 = sGN[row0 + r][tx + dx];
            float g0, g1;
            upk(gn2, g0, g1);
#pragma unroll
            for (int k = 0; k < 4; k++) {
                if (r >= k && r <= k + 4) {   // static predicate, fully unrolled
                    float th0 = tanh_fast(g0 - gc0[k]);
                    float th1 = tanh_fast(g1 - gc1[k]);
                    ull th2 = pk(th0, th1);
                    ull dot2 = fma2(xc2[k], xn2, mul2(yc2[k], yn2));
                    ull u2 = fma2(th2, dot2, dot2);        // (1+tanh)*dot
                    ull t2 = mul2(gn2, u2);                // gn * (1+tanh) * dot
                    xr2[k] = fma2(xn2, t2, xr2[k]);
                    yr2[k] = fma2(yn2, t2, yr2[k]);
                }
            }
        }
    }
}

// -------------------- ETF iterations 1 & 2 (2 channels per block) ------------
__global__ void __launch_bounds__(128) k_iter(int sel) {
    __shared__ ulonglong2 sXY[HHALO][HW];
    __shared__ ull        sGN[HHALO][HW];

    int c0 = blockIdx.z * 2, c1 = c0 + 1;
    const float2* xyiB = sel ? g_xyB : g_xyA;
    float2* xyoB = sel ? g_xyA : g_xyB;

    float ginv0 = 1.0f / __int_as_float(g_gmax[c0]);
    float ginv1 = 1.0f / __int_as_float(g_gmax[c1]);
    int bx0 = blockIdx.x * TW - 2;
    int by0 = blockIdx.y * TH - 2;
    int tid = threadIdx.y * 32 + threadIdx.x;

    load_tile2(sXY, sGN,
               g_gmag + c0 * NPIX, g_gmag + c1 * NPIX,
               xyiB + c0 * NPIX, xyiB + c1 * NPIX,
               ginv0, ginv1, bx0, by0, tid);
    __syncthreads();

    int tx = threadIdx.x;
    int row0 = threadIdx.y * 4;
    int px = blockIdx.x * TW + tx;
    ull xr2[4], yr2[4];
    etf_core2(sXY, sGN, tx, row0, xr2, yr2);

#pragma unroll
    for (int k = 0; k < 4; k++) {
        float x0, x1, y0v, y1;
        upk(xr2[k], x0, x1);
        upk(yr2[k], y0v, y1);
        float i0 = rsqrtf(fmaf(x0, x0, y0v * y0v));
        float i1 = rsqrtf(fmaf(x1, x1, y1 * y1));
        int o = (blockIdx.y * TH + row0 + k) * WW + px;
        xyoB[c0 * NPIX + o] = make_float2(x0 * i0, y0v * i0);
        xyoB[c1 * NPIX + o] = make_float2(x1 * i1, y1 * i1);
    }
}

// -------------------- ETF iteration 3 fused with angle + stats ---------------
// Per-channel stats: fp32 warp shuffles -> smem block stage -> ONE fp64 atomic
// pair per channel per block (measured-best epilogue).
__global__ void __launch_bounds__(128) k_iter3(float* __restrict__ out) {
    __shared__ ulonglong2 sXY[HHALO][HW];
    __shared__ ull        sGN[HHALO][HW];
    __shared__ float      sS[4][4];   // [warp][s0,s20,s1,s21]

    int c0 = blockIdx.z * 2, c1 = c0 + 1;
    float ginv0 = 1.0f / __int_as_float(g_gmax[c0]);
    float ginv1 = 1.0f / __int_as_float(g_gmax[c1]);
    int bx0 = blockIdx.x * TW - 2;
    int by0 = blockIdx.y * TH - 2;
    int tid = threadIdx.y * 32 + threadIdx.x;

    load_tile2(sXY, sGN,
               g_gmag + c0 * NPIX, g_gmag + c1 * NPIX,
               g_xyA + c0 * NPIX, g_xyA + c1 * NPIX,   // iter3 reads A
               ginv0, ginv1, bx0, by0, tid);
    __syncthreads();

    int tx = threadIdx.x;
    int row0 = threadIdx.y * 4;
    int px = blockIdx.x * TW + tx;
    ull xr2[4], yr2[4];
    etf_core2(sXY, sGN, tx, row0, xr2, yr2);

    float s0 = 0.f, s20 = 0.f, s1 = 0.f, s21 = 0.f;
#pragma unroll
    for (int k = 0; k < 4; k++) {
        float x0, x1, y0v, y1;
        upk(xr2[k], x0, x1);
        upk(yr2[k], y0v, y1);
        int o = (blockIdx.y * TH + row0 + k) * WW + px;
        // normalization cancels inside atan(-y/x); divide directly
        float a0 = atan_fast(__fdividef(-y0v, x0)) * 57.2957795131f;
        float a1 = atan_fast(__fdividef(-y1, x1)) * 57.2957795131f;
        out[c0 * NPIX + o] = a0;
        out[c1 * NPIX + o] = a1;
        s0 += a0; s20 = fmaf(a0, a0, s20);
        s1 += a1; s21 = fmaf(a1, a1, s21);
    }

#pragma unroll
    for (int off = 16; off; off >>= 1) {
        s0  += __shfl_xor_sync(0xffffffffu, s0, off);
        s20 += __shfl_xor_sync(0xffffffffu, s20, off);
        s1  += __shfl_xor_sync(0xffffffffu, s1, off);
        s21 += __shfl_xor_sync(0xffffffffu, s21, off);
    }
    int lane = tid & 31, warp = tid >> 5;
    if (lane == 0) {
        sS[warp][0] = s0; sS[warp][1] = s20;
        sS[warp][2] = s1; sS[warp][3] = s21;
    }
    __syncthreads();
    if (tid == 0) {
        float t0 = sS[0][0] + sS[1][0] + sS[2][0] + sS[3][0];
        float t1 = sS[0][1] + sS[1][1] + sS[2][1] + sS[3][1];
        float t2 = sS[0][2] + sS[1][2] + sS[2][2] + sS[3][2];
        float t3 = sS[0][3] + sS[1][3] + sS[2][3] + sS[3][3];
        atomicAdd(&g_sum[c0], (double)t0);     // return unused -> REDG
        atomicAdd(&g_sumsq[c0], (double)t1);
        atomicAdd(&g_sum[c1], (double)t2);
        atomicAdd(&g_sumsq[c1], (double)t3);
    }
}

// -------------------- normalize (float4) + recycle state --------------------
__global__ void __launch_bounds__(256) k_norm(float* __restrict__ out) {
    __shared__ float smu, sinv;
    int c = blockIdx.y;
    if (threadIdx.x == 0) {
        double mean = g_sum[c] / (double)NPIX;
        double var  = g_sumsq[c] / (double)NPIX - mean * mean;
        smu  = (float)mean;
        sinv = (float)(1.0 / sqrt(var + 1e-5));
        if (blockIdx.x == 0) g_gmax[c] = 0;   // recycle for next replay
    }
    __syncthreads();
    float4* o4 = (float4*)(out + c * NPIX);
    int i = blockIdx.x * blockDim.x + threadIdx.x;
    float4 v = o4[i];
    float mu = smu, is = sinv;
    v.x = (v.x - mu) * is;
    v.y = (v.y - mu) * is;
    v.z = (v.z - mu) * is;
    v.w = (v.w - mu) * is;
    o4[i] = v;
}

extern "C" void kernel_launch(void* const* d_in, const int* in_sizes, int n_in,
                              void* d_out, int out_size) {
    const float* img = (const float*)d_in[0];
    float* out = (float*)d_out;

    k_sobel<<<dim3(WW / 32, HH / 32, BC), dim3(32, 8)>>>(img);
    k_iter<<<dim3(WW / TW, HH / TH, BC / 2), dim3(32, 4)>>>(0);   // A -> B
    k_iter<<<dim3(WW / TW, HH / TH, BC / 2), dim3(32, 4)>>>(1);   // B -> A
    k_iter3<<<dim3(WW / TW, HH / TH, BC / 2), dim3(32, 4)>>>(out);// A -> out (+stats)
    k_norm<<<dim3(NPIX / 4 / 256, BC), 256>>>(out);
}